// round 11
// baseline (speedup 1.0000x reference)
#include <cuda_runtime.h>
#include <math.h>
#include <stdint.h>

// Problem dims
#define Bq   8
#define Nn   1000
#define CIN_ 16
#define Hh   64
#define Dd   16
#define XIN_ 80     // CIN + H
#define IG   240    // K * XIN
#define OG   128    // 2H
#define OU   64     // H
#define NCOL 640    // Bq * XIN : batched GEMM N dimension

// Scratch (device globals: allocation-free rule)
__device__ float g_xg[3L * Bq * Nn * IG];    // [z][b][n][240]
__device__ float g_r [3L * Bq * Nn * Hh];    // reset gate
__device__ float g_P0[3L * NCOL * Nn];       // packed operand [z][col][k] (col = b*80+c)
__device__ float g_P1[3L * NCOL * Nn];       // packed t1

__device__ __forceinline__ float f2tf32(float v) {
    float o;
    asm("cvt.rna.tf32.f32 %0, %1;" : "=f"(o) : "f"(v));
    return o;
}

__device__ __forceinline__ void mma_tf32(float* c, const uint32_t* a,
                                         uint32_t b0, uint32_t b1) {
    asm volatile(
        "mma.sync.aligned.m16n8k8.row.col.f32.tf32.tf32.f32 "
        "{%0,%1,%2,%3}, {%4,%5,%6,%7}, {%8,%9}, {%0,%1,%2,%3};"
        : "+f"(c[0]), "+f"(c[1]), "+f"(c[2]), "+f"(c[3])
        : "r"(a[0]), "r"(a[1]), "r"(a[2]), "r"(a[3]), "r"(b0), "r"(b1));
}

// ===========================================================================
// Kernel 1: xs = concat(x, state) -> g_xg[0:80) AND packed g_P0[z][col][k]
// ===========================================================================
__global__ void concat_kernel(const float* __restrict__ x1, const float* __restrict__ x2,
                              const float* __restrict__ x3,
                              const float* __restrict__ s1, const float* __restrict__ s2,
                              const float* __restrict__ s3) {
    const long total = 3L * Bq * Nn * XIN_;
    for (long idx = (long)blockIdx.x * blockDim.x + threadIdx.x; idx < total;
         idx += (long)gridDim.x * blockDim.x) {
        int c = (int)(idx % XIN_);
        long t = idx / XIN_;
        int n = (int)(t % Nn); t /= Nn;
        int b = (int)(t % Bq);
        int z = (int)(t / Bq);
        const float* x = (z == 0) ? x1 : (z == 1) ? x2 : x3;
        const float* s = (z == 0) ? s1 : (z == 1) ? s2 : s3;
        float v = (c < CIN_) ? x[((long)b * Nn + n) * CIN_ + c]
                             : s[((long)b * Nn + n) * Hh + (c - CIN_)];
        g_xg[(((long)z * Bq + b) * Nn + n) * IG + c] = v;
        g_P0[((long)z * NCOL + b * XIN_ + c) * Nn + n] = v;
    }
}

// ===========================================================================
// Kernel 2: tf32 mma.sync GEMM stage (unchanged from R10)
// ===========================================================================
#define KC    32
#define LDK   36

__global__ __launch_bounds__(256)
void gemm_tf32_kernel(const float* __restrict__ S1, const float* __restrict__ S2,
                      const float* __restrict__ S3,
                      const float* __restrict__ Pin, const float* __restrict__ Pprev,
                      float* __restrict__ Pout, int out_off, float alpha, int sub) {
    __shared__ __align__(16) float As[128 * LDK];
    __shared__ __align__(16) float Bs[128 * LDK];

    int z = blockIdx.z;
    const float* S = (z == 0) ? S1 : (z == 1) ? S2 : S3;
    int m0 = blockIdx.x * 128;
    int nt = blockIdx.y;
    const float* Pz = Pin + (long)z * NCOL * Nn;

    int tid = threadIdx.x;
    int wid = tid >> 5, lane = tid & 31;
    int warp_m = wid & 3, warp_n = wid >> 2;
    int g = lane >> 2, tig = lane & 3;

    float acc[2][8][4];
#pragma unroll
    for (int fm = 0; fm < 2; fm++)
#pragma unroll
        for (int fn = 0; fn < 8; fn++)
#pragma unroll
            for (int q = 0; q < 4; q++) acc[fm][fn][q] = 0.f;

    float4 ra[4], rb[4];
    const int NCHUNK = 32;

    auto load_chunk = [&](int j) {
        int kbase = j * KC;
#pragma unroll
        for (int l = 0; l < 4; l++) {
            int linear = tid + l * 256;
            int row = linear >> 3, c4 = linear & 7;
            int k0 = kbase + c4 * 4;
            bool kok = (k0 < Nn);
            float4 va = make_float4(0.f, 0.f, 0.f, 0.f);
            int m = m0 + row;
            if (kok && m < Nn) va = *(const float4*)(S + (long)m * Nn + k0);
            va.x = f2tf32(va.x); va.y = f2tf32(va.y);
            va.z = f2tf32(va.z); va.w = f2tf32(va.w);
            ra[l] = va;
            float4 vb = make_float4(0.f, 0.f, 0.f, 0.f);
            int gc = nt * 128 + row;
            if (kok) vb = *(const float4*)(Pz + (long)gc * Nn + k0);
            vb.x = f2tf32(vb.x); vb.y = f2tf32(vb.y);
            vb.z = f2tf32(vb.z); vb.w = f2tf32(vb.w);
            rb[l] = vb;
        }
    };

    load_chunk(0);

    for (int j = 0; j < NCHUNK; j++) {
        __syncthreads();
#pragma unroll
        for (int l = 0; l < 4; l++) {
            int linear = tid + l * 256;
            int row = linear >> 3, c4 = linear & 7;
            *(float4*)(As + row * LDK + c4 * 4) = ra[l];
            *(float4*)(Bs + row * LDK + c4 * 4) = rb[l];
        }
        __syncthreads();
        if (j + 1 < NCHUNK) load_chunk(j + 1);

#pragma unroll
        for (int ks = 0; ks < 4; ks++) {
            int kk = ks * 8;
            uint32_t afr[2][4];
#pragma unroll
            for (int fm = 0; fm < 2; fm++) {
                int rm = warp_m * 32 + fm * 16;
                const float* ab = As + (rm + g) * LDK + kk + tig;
                afr[fm][0] = __float_as_uint(ab[0]);
                afr[fm][1] = __float_as_uint(ab[8 * LDK]);
                afr[fm][2] = __float_as_uint(ab[4]);
                afr[fm][3] = __float_as_uint(ab[8 * LDK + 4]);
            }
#pragma unroll
            for (int fn = 0; fn < 8; fn++) {
                int nb = warp_n * 64 + fn * 8 + g;
                const float* bb = Bs + nb * LDK + kk + tig;
                uint32_t b0 = __float_as_uint(bb[0]);
                uint32_t b1 = __float_as_uint(bb[4]);
                mma_tf32(acc[0][fn], afr[0], b0, b1);
                mma_tf32(acc[1][fn], afr[1], b0, b1);
            }
        }
    }

    const float* Pprev_z = sub ? (Pprev + (long)z * NCOL * Nn) : nullptr;
    float* Pout_z = Pout ? (Pout + (long)z * NCOL * Nn) : nullptr;
#pragma unroll
    for (int fm = 0; fm < 2; fm++) {
#pragma unroll
        for (int fn = 0; fn < 8; fn++) {
            int m  = m0 + warp_m * 32 + fm * 16 + g;
            int gc = nt * 128 + warp_n * 64 + fn * 8 + tig * 2;
#pragma unroll
            for (int q = 0; q < 4; q++) {
                int mm = m + ((q >= 2) ? 8 : 0);
                int cc = gc + (q & 1);
                if (mm >= Nn) continue;
                float v = alpha * acc[fm][fn][q];
                if (sub) v -= Pprev_z[(long)cc * Nn + mm];
                int b = cc / XIN_, c = cc % XIN_;
                g_xg[(((long)z * Bq + b) * Nn + mm) * IG + out_off + c] = v;
                if (Pout_z) Pout_z[(long)cc * Nn + mm] = v;
            }
        }
    }
}

// ===========================================================================
// Kernel 3: fused gate hypernet. R10->R11: 256 threads = (o:128) x (node-half:2),
// each thread owns 2 nodes -> cr 32 regs, acc 16 regs, half-length dep chains,
// launch_bounds(256,2) -> 16 warps/SM.
// ===========================================================================
#define GGG 4
#define GATE_SMEM ((GGG * IG * 8 + GGG * Dd) * 4)

__global__ __launch_bounds__(256, 2)
void gate_kernel(const float* __restrict__ e1, const float* __restrict__ e2,
                 const float* __restrict__ e3, const float* __restrict__ me,
                 const float* __restrict__ Wg, const float* __restrict__ Bg,
                 const float* __restrict__ st1, const float* __restrict__ st2,
                 const float* __restrict__ st3) {
    extern __shared__ float sm[];
    float* x_s = sm;                       // [GGG][IG][8]
    float* c_s = sm + GGG * IG * 8;        // [GGG][16]

    int z = blockIdx.y;
    int n0 = blockIdx.x * GGG;
    const float* emb = (z == 0) ? e1 : (z == 1) ? e2 : e3;
    const float* st  = (z == 0) ? st1 : (z == 1) ? st2 : st3;

    int tid = threadIdx.x;
    if (tid < GGG * Dd) {   // 64 <= 256
        int g = tid >> 4, d = tid & 15;
        c_s[tid] = emb[(n0 + g) * Dd + d] * me[z * Dd + d];
    }
    for (int idx = tid; idx < GGG * 8 * IG; idx += 256) {
        int i = idx % IG;
        int t = idx / IG;
        int g = t % GGG, b = t / GGG;
        x_s[(g * IG + i) * 8 + b] =
            g_xg[(((long)z * Bq + b) * Nn + n0 + g) * IG + i];
    }
    __syncthreads();

    int o  = tid & 127;       // output column
    int gh = tid >> 7;        // node half: nodes {gh*2, gh*2+1}
    int gbase = gh * 2;

    float4 cr[2][4];
#pragma unroll
    for (int g = 0; g < 2; g++) {
        const float4* cp = (const float4*)(c_s + (gbase + g) * 16);
#pragma unroll
        for (int q = 0; q < 4; q++) cr[g][q] = cp[q];
    }

    float acc[2][8];
#pragma unroll
    for (int g = 0; g < 2; g++)
#pragma unroll
        for (int b = 0; b < 8; b++) acc[g][b] = 0.f;

    float wgv[16], wnx[16];
    {
        const float* wp = Wg + o;
#pragma unroll
        for (int d = 0; d < 16; d++) wnx[d] = wp[(long)d * IG * OG];
    }

    for (int i = 0; i < IG; i++) {
#pragma unroll
        for (int d = 0; d < 16; d++) wgv[d] = wnx[d];
        int ip = (i + 1 < IG) ? (i + 1) : i;
        const float* wp = Wg + (long)ip * OG + o;
#pragma unroll
        for (int d = 0; d < 16; d++) wnx[d] = wp[(long)d * IG * OG];

#pragma unroll
        for (int g = 0; g < 2; g++) {
            float4 c0 = cr[g][0], c1 = cr[g][1], c2 = cr[g][2], c3 = cr[g][3];
            float w = c0.x * wgv[0] + c0.y * wgv[1] + c0.z * wgv[2] + c0.w * wgv[3]
                    + c1.x * wgv[4] + c1.y * wgv[5] + c1.z * wgv[6] + c1.w * wgv[7]
                    + c2.x * wgv[8] + c2.y * wgv[9] + c2.z * wgv[10] + c2.w * wgv[11]
                    + c3.x * wgv[12] + c3.y * wgv[13] + c3.z * wgv[14] + c3.w * wgv[15];
            const float* xp = x_s + ((gbase + g) * IG + i) * 8;
            float4 xa = *(const float4*)(xp);
            float4 xb = *(const float4*)(xp + 4);
            acc[g][0] = fmaf(w, xa.x, acc[g][0]);
            acc[g][1] = fmaf(w, xa.y, acc[g][1]);
            acc[g][2] = fmaf(w, xa.z, acc[g][2]);
            acc[g][3] = fmaf(w, xa.w, acc[g][3]);
            acc[g][4] = fmaf(w, xb.x, acc[g][4]);
            acc[g][5] = fmaf(w, xb.y, acc[g][5]);
            acc[g][6] = fmaf(w, xb.z, acc[g][6]);
            acc[g][7] = fmaf(w, xb.w, acc[g][7]);
        }
    }

#pragma unroll
    for (int g = 0; g < 2; g++) {
        int n = n0 + gbase + g;
        float4 c0 = cr[g][0], c1 = cr[g][1], c2 = cr[g][2], c3 = cr[g][3];
        const float* bp = Bg + o;
        float bias = c0.x * bp[0] + c0.y * bp[OG] + c0.z * bp[2 * OG] + c0.w * bp[3 * OG]
                   + c1.x * bp[4 * OG] + c1.y * bp[5 * OG] + c1.z * bp[6 * OG] + c1.w * bp[7 * OG]
                   + c2.x * bp[8 * OG] + c2.y * bp[9 * OG] + c2.z * bp[10 * OG] + c2.w * bp[11 * OG]
                   + c3.x * bp[12 * OG] + c3.y * bp[13 * OG] + c3.z * bp[14 * OG] + c3.w * bp[15 * OG];
#pragma unroll
        for (int b = 0; b < 8; b++) {
            float v = acc[g][b] + bias;
            float sg = 1.f / (1.f + __expf(-v));
            if (o < Hh) {
                float stv = st[((long)b * Nn + n) * Hh + o];
                float zs = sg * stv;
                g_xg[(((long)z * Bq + b) * Nn + n) * IG + CIN_ + o] = zs;
                g_P0[((long)z * NCOL + b * XIN_ + CIN_ + o) * Nn + n] = zs;
            } else {
                g_r[(((long)z * Bq + b) * Nn + n) * Hh + (o - Hh)] = sg;
            }
        }
    }
}

// ===========================================================================
// Kernel 4: fused update hypernet + GRU mix. R10->R11: 256 threads =
// (o:64) x (node-quarter:4), each thread owns 2 of GGU=8 nodes.
// ===========================================================================
#define GGU 8
#define UPD_SMEM ((GGU * IG * 8 + GGU * Dd) * 4)

__global__ __launch_bounds__(256, 2)
void update_kernel(const float* __restrict__ e1, const float* __restrict__ e2,
                   const float* __restrict__ e3, const float* __restrict__ me,
                   const float* __restrict__ Wu, const float* __restrict__ Bu,
                   const float* __restrict__ st1, const float* __restrict__ st2,
                   const float* __restrict__ st3, float* __restrict__ out) {
    extern __shared__ float sm[];
    float* x_s = sm;                       // [GGU][IG][8]
    float* c_s = sm + GGU * IG * 8;        // [GGU][16]

    int z = blockIdx.y;
    int n0 = blockIdx.x * GGU;
    const float* emb = (z == 0) ? e1 : (z == 1) ? e2 : e3;
    const float* st  = (z == 0) ? st1 : (z == 1) ? st2 : st3;

    int tid = threadIdx.x;
    if (tid < GGU * Dd) {   // 128 <= 256
        int g = tid >> 4, d = tid & 15;
        c_s[tid] = emb[(n0 + g) * Dd + d] * me[z * Dd + d];
    }
    for (int idx = tid; idx < GGU * 8 * IG; idx += 256) {
        int i = idx % IG;
        int t = idx / IG;
        int g = t % GGU, b = t / GGU;
        x_s[(g * IG + i) * 8 + b] =
            g_xg[(((long)z * Bq + b) * Nn + n0 + g) * IG + i];
    }
    __syncthreads();

    int o  = tid & 63;        // output column
    int gq = tid >> 6;        // node quarter: nodes {gq*2, gq*2+1}
    int gbase = gq * 2;

    float4 cr[2][4];
#pragma unroll
    for (int g = 0; g < 2; g++) {
        const float4* cp = (const float4*)(c_s + (gbase + g) * 16);
#pragma unroll
        for (int q = 0; q < 4; q++) cr[g][q] = cp[q];
    }

    float acc[2][8];
#pragma unroll
    for (int g = 0; g < 2; g++)
#pragma unroll
        for (int b = 0; b < 8; b++) acc[g][b] = 0.f;

    float wgv[16], wnx[16];
    {
        const float* wp = Wu + o;
#pragma unroll
        for (int d = 0; d < 16; d++) wnx[d] = wp[(long)d * IG * OU];
    }

    for (int i = 0; i < IG; i++) {
#pragma unroll
        for (int d = 0; d < 16; d++) wgv[d] = wnx[d];
        int ip = (i + 1 < IG) ? (i + 1) : i;
        const float* wp = Wu + (long)ip * OU + o;
#pragma unroll
        for (int d = 0; d < 16; d++) wnx[d] = wp[(long)d * IG * OU];

#pragma unroll
        for (int g = 0; g < 2; g++) {
            float4 c0 = cr[g][0], c1 = cr[g][1], c2 = cr[g][2], c3 = cr[g][3];
            float w = c0.x * wgv[0] + c0.y * wgv[1] + c0.z * wgv[2] + c0.w * wgv[3]
                    + c1.x * wgv[4] + c1.y * wgv[5] + c1.z * wgv[6] + c1.w * wgv[7]
                    + c2.x * wgv[8] + c2.y * wgv[9] + c2.z * wgv[10] + c2.w * wgv[11]
                    + c3.x * wgv[12] + c3.y * wgv[13] + c3.z * wgv[14] + c3.w * wgv[15];
            const float* xp = x_s + ((gbase + g) * IG + i) * 8;
            float4 xa = *(const float4*)(xp);
            float4 xb = *(const float4*)(xp + 4);
            acc[g][0] = fmaf(w, xa.x, acc[g][0]);
            acc[g][1] = fmaf(w, xa.y, acc[g][1]);
            acc[g][2] = fmaf(w, xa.z, acc[g][2]);
            acc[g][3] = fmaf(w, xa.w, acc[g][3]);
            acc[g][4] = fmaf(w, xb.x, acc[g][4]);
            acc[g][5] = fmaf(w, xb.y, acc[g][5]);
            acc[g][6] = fmaf(w, xb.z, acc[g][6]);
            acc[g][7] = fmaf(w, xb.w, acc[g][7]);
        }
    }

#pragma unroll
    for (int g = 0; g < 2; g++) {
        int n = n0 + gbase + g;
        float4 c0 = cr[g][0], c1 = cr[g][1], c2 = cr[g][2], c3 = cr[g][3];
        const float* bp = Bu + o;
        float bias = c0.x * bp[0] + c0.y * bp[OU] + c0.z * bp[2 * OU] + c0.w * bp[3 * OU]
                   + c1.x * bp[4 * OU] + c1.y * bp[5 * OU] + c1.z * bp[6 * OU] + c1.w * bp[7 * OU]
                   + c2.x * bp[8 * OU] + c2.y * bp[9 * OU] + c2.z * bp[10 * OU] + c2.w * bp[11 * OU]
                   + c3.x * bp[12 * OU] + c3.y * bp[13 * OU] + c3.z * bp[14 * OU] + c3.w * bp[15 * OU];
#pragma unroll
        for (int b = 0; b < 8; b++) {
            float hc = tanhf(acc[g][b] + bias);
            long hidx = (((long)z * Bq + b) * Nn + n) * Hh + o;
            float r = g_r[hidx];
            float stv = st[((long)b * Nn + n) * Hh + o];
            out[hidx] = r * stv + (1.f - r) * hc;
        }
    }
}

// ===========================================================================
extern "C" void kernel_launch(void* const* d_in, const int* in_sizes, int n_in,
                              void* d_out, int out_size) {
    const float* x1 = (const float*)d_in[0];
    const float* x2 = (const float*)d_in[1];
    const float* x3 = (const float*)d_in[2];
    const float* s1 = (const float*)d_in[3];
    const float* s2 = (const float*)d_in[4];
    const float* s3 = (const float*)d_in[5];
    const float* A1 = (const float*)d_in[6];
    const float* A2 = (const float*)d_in[7];
    const float* A3 = (const float*)d_in[8];
    const float* e1 = (const float*)d_in[9];
    const float* e2 = (const float*)d_in[10];
    const float* e3 = (const float*)d_in[11];
    const float* me = (const float*)d_in[12];
    const float* Wg = (const float*)d_in[13];
    const float* Bg = (const float*)d_in[14];
    const float* Wu = (const float*)d_in[15];
    const float* Bu = (const float*)d_in[16];
    float* out = (float*)d_out;

    cudaFuncSetAttribute((const void*)gate_kernel,
                         cudaFuncAttributeMaxDynamicSharedMemorySize, GATE_SMEM);
    cudaFuncSetAttribute((const void*)update_kernel,
                         cudaFuncAttributeMaxDynamicSharedMemorySize, UPD_SMEM);

    float* P0;  cudaGetSymbolAddress((void**)&P0, g_P0);
    float* P1;  cudaGetSymbolAddress((void**)&P1, g_P1);

    dim3 gemm_grid(8, 5, 3);              // M-tiles x N-tiles x modes
    dim3 gg(Nn / GGG, 3);                 // 250 x 3
    dim3 gu(Nn / GGU, 3);                 // 125 x 3

    // ---- gate GCN ----
    concat_kernel<<<512, 256>>>(x1, x2, x3, s1, s2, s3);
    // t1 = S @ xs            -> g_xg[80:160] + packed P1
    gemm_tf32_kernel<<<gemm_grid, 256>>>(A1, A2, A3, P0, nullptr, P1, 80, 1.f, 0);
    // t2 = 2 S @ t1 - xs     -> g_xg[160:240]
    gemm_tf32_kernel<<<gemm_grid, 256>>>(A1, A2, A3, P1, P0, nullptr, 160, 2.f, 1);
    gate_kernel<<<gg, 256, GATE_SMEM>>>(e1, e2, e3, me, Wg, Bg, s1, s2, s3);
    // ---- candidate GCN (P0 cols 16:80 now hold z*state; cols 0:16 still x) ----
    gemm_tf32_kernel<<<gemm_grid, 256>>>(A1, A2, A3, P0, nullptr, P1, 80, 1.f, 0);
    gemm_tf32_kernel<<<gemm_grid, 256>>>(A1, A2, A3, P1, P0, nullptr, 160, 2.f, 1);
    update_kernel<<<gu, 256, UPD_SMEM>>>(e1, e2, e3, me, Wu, Bu, s1, s2, s3, out);
}

// round 13
// speedup vs baseline: 1.1897x; 1.1897x over previous
#include <cuda_runtime.h>
#include <math.h>
#include <stdint.h>

// Problem dims
#define Bq   8
#define Nn   1000
#define CIN_ 16
#define Hh   64
#define Dd   16
#define XIN_ 80     // CIN + H
#define IG   240    // K * XIN
#define OG   128    // 2H
#define OU   64     // H
#define NCOL 640    // Bq * XIN : batched GEMM N dimension

// Scratch (device globals: allocation-free rule)
__device__ float g_xg[3L * Bq * Nn * IG];    // [z][b][n][240]
__device__ float g_r [3L * Bq * Nn * Hh];    // reset gate
__device__ float g_P0[3L * NCOL * Nn];       // packed operand [z][col][k] (col = b*80+c)
__device__ float g_P1[3L * NCOL * Nn];       // packed t1

__device__ __forceinline__ float f2tf32(float v) {
    float o;
    asm("cvt.rna.tf32.f32 %0, %1;" : "=f"(o) : "f"(v));
    return o;
}

__device__ __forceinline__ void mma_tf32(float* c, const uint32_t* a,
                                         uint32_t b0, uint32_t b1) {
    asm volatile(
        "mma.sync.aligned.m16n8k8.row.col.f32.tf32.tf32.f32 "
        "{%0,%1,%2,%3}, {%4,%5,%6,%7}, {%8,%9}, {%0,%1,%2,%3};"
        : "+f"(c[0]), "+f"(c[1]), "+f"(c[2]), "+f"(c[3])
        : "r"(a[0]), "r"(a[1]), "r"(a[2]), "r"(a[3]), "r"(b0), "r"(b1));
}

__device__ __forceinline__ uint32_t smem_u32(const void* p) {
    uint32_t a;
    asm("{ .reg .u64 t; cvta.to.shared.u64 t, %1; cvt.u32.u64 %0, t; }"
        : "=r"(a) : "l"(p));
    return a;
}
__device__ __forceinline__ void cp_async16(uint32_t dst, const void* src) {
    asm volatile("cp.async.ca.shared.global [%0], [%1], 16;" :: "r"(dst), "l"(src));
}
#define CP_COMMIT() asm volatile("cp.async.commit_group;" ::: "memory")
#define CP_WAIT2()  asm volatile("cp.async.wait_group 2;" ::: "memory")

// ===========================================================================
// Kernel 1: xs = concat(x, state) -> g_xg[0:80) AND packed g_P0[z][col][k]
// ===========================================================================
__global__ void concat_kernel(const float* __restrict__ x1, const float* __restrict__ x2,
                              const float* __restrict__ x3,
                              const float* __restrict__ s1, const float* __restrict__ s2,
                              const float* __restrict__ s3) {
    const long total = 3L * Bq * Nn * XIN_;
    for (long idx = (long)blockIdx.x * blockDim.x + threadIdx.x; idx < total;
         idx += (long)gridDim.x * blockDim.x) {
        int c = (int)(idx % XIN_);
        long t = idx / XIN_;
        int n = (int)(t % Nn); t /= Nn;
        int b = (int)(t % Bq);
        int z = (int)(t / Bq);
        const float* x = (z == 0) ? x1 : (z == 1) ? x2 : x3;
        const float* s = (z == 0) ? s1 : (z == 1) ? s2 : s3;
        float v = (c < CIN_) ? x[((long)b * Nn + n) * CIN_ + c]
                             : s[((long)b * Nn + n) * Hh + (c - CIN_)];
        g_xg[(((long)z * Bq + b) * Nn + n) * IG + c] = v;
        g_P0[((long)z * NCOL + b * XIN_ + c) * Nn + n] = v;
    }
}

// ===========================================================================
// Kernel 2: tf32 mma.sync GEMM stage (unchanged from R10 — at mma.sync floor)
// ===========================================================================
#define KC    32
#define LDK   36

__global__ __launch_bounds__(256)
void gemm_tf32_kernel(const float* __restrict__ S1, const float* __restrict__ S2,
                      const float* __restrict__ S3,
                      const float* __restrict__ Pin, const float* __restrict__ Pprev,
                      float* __restrict__ Pout, int out_off, float alpha, int sub) {
    __shared__ __align__(16) float As[128 * LDK];
    __shared__ __align__(16) float Bs[128 * LDK];

    int z = blockIdx.z;
    const float* S = (z == 0) ? S1 : (z == 1) ? S2 : S3;
    int m0 = blockIdx.x * 128;
    int nt = blockIdx.y;
    const float* Pz = Pin + (long)z * NCOL * Nn;

    int tid = threadIdx.x;
    int wid = tid >> 5, lane = tid & 31;
    int warp_m = wid & 3, warp_n = wid >> 2;
    int g = lane >> 2, tig = lane & 3;

    float acc[2][8][4];
#pragma unroll
    for (int fm = 0; fm < 2; fm++)
#pragma unroll
        for (int fn = 0; fn < 8; fn++)
#pragma unroll
            for (int q = 0; q < 4; q++) acc[fm][fn][q] = 0.f;

    float4 ra[4], rb[4];
    const int NCHUNK = 32;

    auto load_chunk = [&](int j) {
        int kbase = j * KC;
#pragma unroll
        for (int l = 0; l < 4; l++) {
            int linear = tid + l * 256;
            int row = linear >> 3, c4 = linear & 7;
            int k0 = kbase + c4 * 4;
            bool kok = (k0 < Nn);
            float4 va = make_float4(0.f, 0.f, 0.f, 0.f);
            int m = m0 + row;
            if (kok && m < Nn) va = *(const float4*)(S + (long)m * Nn + k0);
            va.x = f2tf32(va.x); va.y = f2tf32(va.y);
            va.z = f2tf32(va.z); va.w = f2tf32(va.w);
            ra[l] = va;
            float4 vb = make_float4(0.f, 0.f, 0.f, 0.f);
            int gc = nt * 128 + row;
            if (kok) vb = *(const float4*)(Pz + (long)gc * Nn + k0);
            vb.x = f2tf32(vb.x); vb.y = f2tf32(vb.y);
            vb.z = f2tf32(vb.z); vb.w = f2tf32(vb.w);
            rb[l] = vb;
        }
    };

    load_chunk(0);

    for (int j = 0; j < NCHUNK; j++) {
        __syncthreads();
#pragma unroll
        for (int l = 0; l < 4; l++) {
            int linear = tid + l * 256;
            int row = linear >> 3, c4 = linear & 7;
            *(float4*)(As + row * LDK + c4 * 4) = ra[l];
            *(float4*)(Bs + row * LDK + c4 * 4) = rb[l];
        }
        __syncthreads();
        if (j + 1 < NCHUNK) load_chunk(j + 1);

#pragma unroll
        for (int ks = 0; ks < 4; ks++) {
            int kk = ks * 8;
            uint32_t afr[2][4];
#pragma unroll
            for (int fm = 0; fm < 2; fm++) {
                int rm = warp_m * 32 + fm * 16;
                const float* ab = As + (rm + g) * LDK + kk + tig;
                afr[fm][0] = __float_as_uint(ab[0]);
                afr[fm][1] = __float_as_uint(ab[8 * LDK]);
                afr[fm][2] = __float_as_uint(ab[4]);
                afr[fm][3] = __float_as_uint(ab[8 * LDK + 4]);
            }
#pragma unroll
            for (int fn = 0; fn < 8; fn++) {
                int nb = warp_n * 64 + fn * 8 + g;
                const float* bb = Bs + nb * LDK + kk + tig;
                uint32_t b0 = __float_as_uint(bb[0]);
                uint32_t b1 = __float_as_uint(bb[4]);
                mma_tf32(acc[0][fn], afr[0], b0, b1);
                mma_tf32(acc[1][fn], afr[1], b0, b1);
            }
        }
    }

    const float* Pprev_z = sub ? (Pprev + (long)z * NCOL * Nn) : nullptr;
    float* Pout_z = Pout ? (Pout + (long)z * NCOL * Nn) : nullptr;
#pragma unroll
    for (int fm = 0; fm < 2; fm++) {
#pragma unroll
        for (int fn = 0; fn < 8; fn++) {
            int m  = m0 + warp_m * 32 + fm * 16 + g;
            int gc = nt * 128 + warp_n * 64 + fn * 8 + tig * 2;
#pragma unroll
            for (int q = 0; q < 4; q++) {
                int mm = m + ((q >= 2) ? 8 : 0);
                int cc = gc + (q & 1);
                if (mm >= Nn) continue;
                float v = alpha * acc[fm][fn][q];
                if (sub) v -= Pprev_z[(long)cc * Nn + mm];
                int b = cc / XIN_, c = cc % XIN_;
                g_xg[(((long)z * Bq + b) * Nn + mm) * IG + out_off + c] = v;
                if (Pout_z) Pout_z[(long)cc * Nn + mm] = v;
            }
        }
    }
}

// ===========================================================================
// Kernel 3: fused gate hypernet. R12: back to R10 shape (128 thr, GGG=4) +
// cp.async 4-stage smem ring for the Wg pool stream (replaces 16 scalar LDG/i
// with 4 LDGSTS.128/i + 16 conflict-free LDS.32, prefetch depth 3 iterations).
// smem: x_s 30720B + c_s 256B + ring 32768B = 63744B -> 3 blocks/SM.
// ===========================================================================
#define GGG 4
#define RING_OFF   (GGG * IG * 8 + GGG * Dd)    // floats: 7744
#define GATE_SMEM  ((RING_OFF + 4 * Dd * OG) * 4)  // + 4 stages * 2048 floats

__global__ __launch_bounds__(128, 3)
void gate_kernel(const float* __restrict__ e1, const float* __restrict__ e2,
                 const float* __restrict__ e3, const float* __restrict__ me,
                 const float* __restrict__ Wg, const float* __restrict__ Bg,
                 const float* __restrict__ st1, const float* __restrict__ st2,
                 const float* __restrict__ st3) {
    extern __shared__ float sm[];
    float* x_s  = sm;                      // [GGG][IG][8]
    float* c_s  = sm + GGG * IG * 8;       // [GGG][16]
    float* ring = sm + RING_OFF;           // [4][16][128]
    uint32_t ring_u32 = smem_u32(ring);

    int z = blockIdx.y;
    int n0 = blockIdx.x * GGG;
    const float* emb = (z == 0) ? e1 : (z == 1) ? e2 : e3;
    const float* st  = (z == 0) ? st1 : (z == 1) ? st2 : st3;

    int tid = threadIdx.x;

    // stage loader: pool slice Wg[:, i, :] (16 rows x 512B) -> ring slot
    auto issue_stage = [&](int i, int slot) {
#pragma unroll
        for (int l = 0; l < 4; l++) {
            int seg = tid + l * 128;        // 0..511 (16B segments)
            int d   = seg >> 5;             // 0..15
            int c4  = seg & 31;             // 16B chunk in 512B row
            cp_async16(ring_u32 + (uint32_t)(slot * 2048 + d * 128 + c4 * 4) * 4,
                       Wg + (long)d * IG * OG + (long)i * OG + c4 * 4);
        }
        CP_COMMIT();
    };

    // prime 3 stages while filling x_s
    issue_stage(0, 0);
    issue_stage(1, 1);
    issue_stage(2, 2);

    if (tid < GGG * Dd) {   // 64 <= 128
        int g = tid >> 4, d = tid & 15;
        c_s[tid] = emb[(n0 + g) * Dd + d] * me[z * Dd + d];
    }
    for (int idx = tid; idx < GGG * 8 * IG; idx += 128) {
        int i = idx % IG;
        int t = idx / IG;
        int g = t % GGG, b = t / GGG;
        x_s[(g * IG + i) * 8 + b] =
            g_xg[(((long)z * Bq + b) * Nn + n0 + g) * IG + i];
    }
    __syncthreads();

    int o = tid;  // 0..127
    float4 cr[GGG][4];
#pragma unroll
    for (int g = 0; g < GGG; g++) {
        const float4* cp = (const float4*)(c_s + g * 16);
#pragma unroll
        for (int q = 0; q < 4; q++) cr[g][q] = cp[q];
    }

    float acc[GGG][8];
#pragma unroll
    for (int g = 0; g < GGG; g++)
#pragma unroll
        for (int b = 0; b < 8; b++) acc[g][b] = 0.f;

    for (int i = 0; i < IG; i++) {
        int slot = i & 3;
        CP_WAIT2();            // stage i landed (own portion)
        __syncthreads();       // all portions visible; readers of stage i-1 done

        float wgv[16];
        const float* rs = ring + slot * 2048 + o;
#pragma unroll
        for (int d = 0; d < 16; d++) wgv[d] = rs[d * 128];

        if (i + 3 < IG) issue_stage(i + 3, (i + 3) & 3);

#pragma unroll
        for (int g = 0; g < GGG; g++) {
            float4 c0 = cr[g][0], c1 = cr[g][1], c2 = cr[g][2], c3 = cr[g][3];
            float w = c0.x * wgv[0] + c0.y * wgv[1] + c0.z * wgv[2] + c0.w * wgv[3]
                    + c1.x * wgv[4] + c1.y * wgv[5] + c1.z * wgv[6] + c1.w * wgv[7]
                    + c2.x * wgv[8] + c2.y * wgv[9] + c2.z * wgv[10] + c2.w * wgv[11]
                    + c3.x * wgv[12] + c3.y * wgv[13] + c3.z * wgv[14] + c3.w * wgv[15];
            const float* xp = x_s + (g * IG + i) * 8;
            float4 xa = *(const float4*)(xp);
            float4 xb = *(const float4*)(xp + 4);
            acc[g][0] = fmaf(w, xa.x, acc[g][0]);
            acc[g][1] = fmaf(w, xa.y, acc[g][1]);
            acc[g][2] = fmaf(w, xa.z, acc[g][2]);
            acc[g][3] = fmaf(w, xa.w, acc[g][3]);
            acc[g][4] = fmaf(w, xb.x, acc[g][4]);
            acc[g][5] = fmaf(w, xb.y, acc[g][5]);
            acc[g][6] = fmaf(w, xb.z, acc[g][6]);
            acc[g][7] = fmaf(w, xb.w, acc[g][7]);
        }
    }

#pragma unroll
    for (int g = 0; g < GGG; g++) {
        int n = n0 + g;
        float4 c0 = cr[g][0], c1 = cr[g][1], c2 = cr[g][2], c3 = cr[g][3];
        const float* bp = Bg + o;
        float bias = c0.x * bp[0] + c0.y * bp[OG] + c0.z * bp[2 * OG] + c0.w * bp[3 * OG]
                   + c1.x * bp[4 * OG] + c1.y * bp[5 * OG] + c1.z * bp[6 * OG] + c1.w * bp[7 * OG]
                   + c2.x * bp[8 * OG] + c2.y * bp[9 * OG] + c2.z * bp[10 * OG] + c2.w * bp[11 * OG]
                   + c3.x * bp[12 * OG] + c3.y * bp[13 * OG] + c3.z * bp[14 * OG] + c3.w * bp[15 * OG];
#pragma unroll
        for (int b = 0; b < 8; b++) {
            float v = acc[g][b] + bias;
            float sg = 1.f / (1.f + __expf(-v));
            if (o < Hh) {
                float stv = st[((long)b * Nn + n) * Hh + o];
                float zs = sg * stv;
                g_xg[(((long)z * Bq + b) * Nn + n) * IG + CIN_ + o] = zs;
                g_P0[((long)z * NCOL + b * XIN_ + CIN_ + o) * Nn + n] = zs;
            } else {
                g_r[(((long)z * Bq + b) * Nn + n) * Hh + (o - Hh)] = sg;
            }
        }
    }
}

// ===========================================================================
// Kernel 4: fused update hypernet + GRU mix (R10 version, reverted from R11)
// 128 threads = (o:64) x (g-half:2), GGU=8, combine computed once per (g,i,o).
// ===========================================================================
#define GGU 8
#define UPD_SMEM ((GGU * IG * 8 + GGU * Dd) * 4)

__global__ __launch_bounds__(128, 3)
void update_kernel(const float* __restrict__ e1, const float* __restrict__ e2,
                   const float* __restrict__ e3, const float* __restrict__ me,
                   const float* __restrict__ Wu, const float* __restrict__ Bu,
                   const float* __restrict__ st1, const float* __restrict__ st2,
                   const float* __restrict__ st3, float* __restrict__ out) {
    extern __shared__ float sm[];
    float* x_s = sm;
    float* c_s = sm + GGU * IG * 8;

    int z = blockIdx.y;
    int n0 = blockIdx.x * GGU;
    const float* emb = (z == 0) ? e1 : (z == 1) ? e2 : e3;
    const float* st  = (z == 0) ? st1 : (z == 1) ? st2 : st3;

    int tid = threadIdx.x;
    if (tid < GGU * Dd) {   // 128 threads cover 128 entries
        int g = tid >> 4, d = tid & 15;
        c_s[tid] = emb[(n0 + g) * Dd + d] * me[z * Dd + d];
    }
    for (int idx = tid; idx < GGU * 8 * IG; idx += 128) {
        int i = idx % IG;
        int t = idx / IG;
        int g = t % GGU, b = t / GGU;
        x_s[(g * IG + i) * 8 + b] =
            g_xg[(((long)z * Bq + b) * Nn + n0 + g) * IG + i];
    }
    __syncthreads();

    int o  = tid & 63;
    int gh = tid >> 6;
    int gbase = gh * 4;

    float4 cr[4][4];
#pragma unroll
    for (int g = 0; g < 4; g++) {
        const float4* cp = (const float4*)(c_s + (gbase + g) * 16);
#pragma unroll
        for (int q = 0; q < 4; q++) cr[g][q] = cp[q];
    }

    float acc[4][8];
#pragma unroll
    for (int g = 0; g < 4; g++)
#pragma unroll
        for (int b = 0; b < 8; b++) acc[g][b] = 0.f;

    float wgv[16], wnx[16];
    {
        const float* wp = Wu + o;
#pragma unroll
        for (int d = 0; d < 16; d++) wnx[d] = wp[(long)d * IG * OU];
    }

    for (int i = 0; i < IG; i++) {
#pragma unroll
        for (int d = 0; d < 16; d++) wgv[d] = wnx[d];
        int ip = (i + 1 < IG) ? (i + 1) : i;
        const float* wp = Wu + (long)ip * OU + o;
#pragma unroll
        for (int d = 0; d < 16; d++) wnx[d] = wp[(long)d * IG * OU];

#pragma unroll
        for (int g = 0; g < 4; g++) {
            float4 c0 = cr[g][0], c1 = cr[g][1], c2 = cr[g][2], c3 = cr[g][3];
            float w = c0.x * wgv[0] + c0.y * wgv[1] + c0.z * wgv[2] + c0.w * wgv[3]
                    + c1.x * wgv[4] + c1.y * wgv[5] + c1.z * wgv[6] + c1.w * wgv[7]
                    + c2.x * wgv[8] + c2.y * wgv[9] + c2.z * wgv[10] + c2.w * wgv[11]
                    + c3.x * wgv[12] + c3.y * wgv[13] + c3.z * wgv[14] + c3.w * wgv[15];
            const float* xp = x_s + ((gbase + g) * IG + i) * 8;
            float4 xa = *(const float4*)(xp);
            float4 xb = *(const float4*)(xp + 4);
            acc[g][0] = fmaf(w, xa.x, acc[g][0]);
            acc[g][1] = fmaf(w, xa.y, acc[g][1]);
            acc[g][2] = fmaf(w, xa.z, acc[g][2]);
            acc[g][3] = fmaf(w, xa.w, acc[g][3]);
            acc[g][4] = fmaf(w, xb.x, acc[g][4]);
            acc[g][5] = fmaf(w, xb.y, acc[g][5]);
            acc[g][6] = fmaf(w, xb.z, acc[g][6]);
            acc[g][7] = fmaf(w, xb.w, acc[g][7]);
        }
    }

#pragma unroll
    for (int g = 0; g < 4; g++) {
        int n = n0 + gbase + g;
        float4 c0 = cr[g][0], c1 = cr[g][1], c2 = cr[g][2], c3 = cr[g][3];
        const float* bp = Bu + o;
        float bias = c0.x * bp[0] + c0.y * bp[OU] + c0.z * bp[2 * OU] + c0.w * bp[3 * OU]
                   + c1.x * bp[4 * OU] + c1.y * bp[5 * OU] + c1.z * bp[6 * OU] + c1.w * bp[7 * OU]
                   + c2.x * bp[8 * OU] + c2.y * bp[9 * OU] + c2.z * bp[10 * OU] + c2.w * bp[11 * OU]
                   + c3.x * bp[12 * OU] + c3.y * bp[13 * OU] + c3.z * bp[14 * OU] + c3.w * bp[15 * OU];
#pragma unroll
        for (int b = 0; b < 8; b++) {
            float hc = tanhf(acc[g][b] + bias);
            long hidx = (((long)z * Bq + b) * Nn + n) * Hh + o;
            float r = g_r[hidx];
            float stv = st[((long)b * Nn + n) * Hh + o];
            out[hidx] = r * stv + (1.f - r) * hc;
        }
    }
}

// ===========================================================================
extern "C" void kernel_launch(void* const* d_in, const int* in_sizes, int n_in,
                              void* d_out, int out_size) {
    const float* x1 = (const float*)d_in[0];
    const float* x2 = (const float*)d_in[1];
    const float* x3 = (const float*)d_in[2];
    const float* s1 = (const float*)d_in[3];
    const float* s2 = (const float*)d_in[4];
    const float* s3 = (const float*)d_in[5];
    const float* A1 = (const float*)d_in[6];
    const float* A2 = (const float*)d_in[7];
    const float* A3 = (const float*)d_in[8];
    const float* e1 = (const float*)d_in[9];
    const float* e2 = (const float*)d_in[10];
    const float* e3 = (const float*)d_in[11];
    const float* me = (const float*)d_in[12];
    const float* Wg = (const float*)d_in[13];
    const float* Bg = (const float*)d_in[14];
    const float* Wu = (const float*)d_in[15];
    const float* Bu = (const float*)d_in[16];
    float* out = (float*)d_out;

    cudaFuncSetAttribute((const void*)gate_kernel,
                         cudaFuncAttributeMaxDynamicSharedMemorySize, GATE_SMEM);
    cudaFuncSetAttribute((const void*)update_kernel,
                         cudaFuncAttributeMaxDynamicSharedMemorySize, UPD_SMEM);

    float* P0;  cudaGetSymbolAddress((void**)&P0, g_P0);
    float* P1;  cudaGetSymbolAddress((void**)&P1, g_P1);

    dim3 gemm_grid(8, 5, 3);              // M-tiles x N-tiles x modes
    dim3 gg(Nn / GGG, 3);                 // 250 x 3
    dim3 gu(Nn / GGU, 3);                 // 125 x 3

    // ---- gate GCN ----
    concat_kernel<<<512, 256>>>(x1, x2, x3, s1, s2, s3);
    // t1 = S @ xs            -> g_xg[80:160] + packed P1
    gemm_tf32_kernel<<<gemm_grid, 256>>>(A1, A2, A3, P0, nullptr, P1, 80, 1.f, 0);
    // t2 = 2 S @ t1 - xs     -> g_xg[160:240]
    gemm_tf32_kernel<<<gemm_grid, 256>>>(A1, A2, A3, P1, P0, nullptr, 160, 2.f, 1);
    gate_kernel<<<gg, 128, GATE_SMEM>>>(e1, e2, e3, me, Wg, Bg, s1, s2, s3);
    // ---- candidate GCN (P0 cols 16:80 now hold z*state; cols 0:16 still x) ----
    gemm_tf32_kernel<<<gemm_grid, 256>>>(A1, A2, A3, P0, nullptr, P1, 80, 1.f, 0);
    gemm_tf32_kernel<<<gemm_grid, 256>>>(A1, A2, A3, P1, P0, nullptr, 160, 2.f, 1);
    update_kernel<<<gu, 128, UPD_SMEM>>>(e1, e2, e3, me, Wu, Bu, s1, s2, s3, out);
}

// round 15
// speedup vs baseline: 1.2774x; 1.0737x over previous
#include <cuda_runtime.h>
#include <math.h>
#include <stdint.h>

// Problem dims
#define Bq   8
#define Nn   1000
#define CIN_ 16
#define Hh   64
#define Dd   16
#define XIN_ 80     // CIN + H
#define IG   240    // K * XIN
#define OG   128    // 2H
#define OU   64     // H
#define NCOL 640    // Bq * XIN : batched GEMM N dimension

// Scratch (device globals: allocation-free rule)
__device__ float g_xg[3L * Bq * Nn * IG];    // [z][b][n][240]
__device__ float g_r [3L * Bq * Nn * Hh];    // reset gate
__device__ float g_P0[3L * NCOL * Nn];       // packed operand [z][col][k] (col = b*80+c)
__device__ float g_P1[3L * NCOL * Nn];       // packed t1

typedef unsigned long long u64t;

__device__ __forceinline__ float f2tf32(float v) {
    float o;
    asm("cvt.rna.tf32.f32 %0, %1;" : "=f"(o) : "f"(v));
    return o;
}

__device__ __forceinline__ void mma_tf32(float* c, const uint32_t* a,
                                         uint32_t b0, uint32_t b1) {
    asm volatile(
        "mma.sync.aligned.m16n8k8.row.col.f32.tf32.tf32.f32 "
        "{%0,%1,%2,%3}, {%4,%5,%6,%7}, {%8,%9}, {%0,%1,%2,%3};"
        : "+f"(c[0]), "+f"(c[1]), "+f"(c[2]), "+f"(c[3])
        : "r"(a[0]), "r"(a[1]), "r"(a[2]), "r"(a[3]), "r"(b0), "r"(b1));
}

__device__ __forceinline__ uint32_t smem_u32(const void* p) {
    uint32_t a;
    asm("{ .reg .u64 t; cvta.to.shared.u64 t, %1; cvt.u32.u64 %0, t; }"
        : "=r"(a) : "l"(p));
    return a;
}
__device__ __forceinline__ void cp_async16(uint32_t dst, const void* src) {
    asm volatile("cp.async.ca.shared.global [%0], [%1], 16;" :: "r"(dst), "l"(src));
}
#define CP_COMMIT() asm volatile("cp.async.commit_group;" ::: "memory")
#define CP_WAIT2()  asm volatile("cp.async.wait_group 2;" ::: "memory")

// ---- packed f32x2 helpers (base sm_100+ PTX; OK on compute_103) ----
__device__ __forceinline__ void ffma2(u64t& d, u64t a, u64t b) {
    asm("fma.rn.f32x2 %0, %1, %2, %0;" : "+l"(d) : "l"(a), "l"(b));
}
__device__ __forceinline__ u64t pack2(float lo, float hi) {
    u64t r;
    asm("mov.b64 %0, {%1, %2};" : "=l"(r) : "f"(lo), "f"(hi));
    return r;
}
__device__ __forceinline__ void unpack2(float& lo, float& hi, u64t v) {
    asm("mov.b64 {%0, %1}, %2;" : "=f"(lo), "=f"(hi) : "l"(v));
}

// ===========================================================================
// Kernel 1: xs = concat(x, state) -> g_xg[0:80) AND packed g_P0[z][col][k]
// ===========================================================================
__global__ void concat_kernel(const float* __restrict__ x1, const float* __restrict__ x2,
                              const float* __restrict__ x3,
                              const float* __restrict__ s1, const float* __restrict__ s2,
                              const float* __restrict__ s3) {
    const long total = 3L * Bq * Nn * XIN_;
    for (long idx = (long)blockIdx.x * blockDim.x + threadIdx.x; idx < total;
         idx += (long)gridDim.x * blockDim.x) {
        int c = (int)(idx % XIN_);
        long t = idx / XIN_;
        int n = (int)(t % Nn); t /= Nn;
        int b = (int)(t % Bq);
        int z = (int)(t / Bq);
        const float* x = (z == 0) ? x1 : (z == 1) ? x2 : x3;
        const float* s = (z == 0) ? s1 : (z == 1) ? s2 : s3;
        float v = (c < CIN_) ? x[((long)b * Nn + n) * CIN_ + c]
                             : s[((long)b * Nn + n) * Hh + (c - CIN_)];
        g_xg[(((long)z * Bq + b) * Nn + n) * IG + c] = v;
        g_P0[((long)z * NCOL + b * XIN_ + c) * Nn + n] = v;
    }
}

// ===========================================================================
// Kernel 2: tf32 mma.sync GEMM stage (unchanged — at mma.sync floor)
// ===========================================================================
#define KC    32
#define LDK   36

__global__ __launch_bounds__(256)
void gemm_tf32_kernel(const float* __restrict__ S1, const float* __restrict__ S2,
                      const float* __restrict__ S3,
                      const float* __restrict__ Pin, const float* __restrict__ Pprev,
                      float* __restrict__ Pout, int out_off, float alpha, int sub) {
    __shared__ __align__(16) float As[128 * LDK];
    __shared__ __align__(16) float Bs[128 * LDK];

    int z = blockIdx.z;
    const float* S = (z == 0) ? S1 : (z == 1) ? S2 : S3;
    int m0 = blockIdx.x * 128;
    int nt = blockIdx.y;
    const float* Pz = Pin + (long)z * NCOL * Nn;

    int tid = threadIdx.x;
    int wid = tid >> 5, lane = tid & 31;
    int warp_m = wid & 3, warp_n = wid >> 2;
    int g = lane >> 2, tig = lane & 3;

    float acc[2][8][4];
#pragma unroll
    for (int fm = 0; fm < 2; fm++)
#pragma unroll
        for (int fn = 0; fn < 8; fn++)
#pragma unroll
            for (int q = 0; q < 4; q++) acc[fm][fn][q] = 0.f;

    float4 ra[4], rb[4];
    const int NCHUNK = 32;

    auto load_chunk = [&](int j) {
        int kbase = j * KC;
#pragma unroll
        for (int l = 0; l < 4; l++) {
            int linear = tid + l * 256;
            int row = linear >> 3, c4 = linear & 7;
            int k0 = kbase + c4 * 4;
            bool kok = (k0 < Nn);
            float4 va = make_float4(0.f, 0.f, 0.f, 0.f);
            int m = m0 + row;
            if (kok && m < Nn) va = *(const float4*)(S + (long)m * Nn + k0);
            va.x = f2tf32(va.x); va.y = f2tf32(va.y);
            va.z = f2tf32(va.z); va.w = f2tf32(va.w);
            ra[l] = va;
            float4 vb = make_float4(0.f, 0.f, 0.f, 0.f);
            int gc = nt * 128 + row;
            if (kok) vb = *(const float4*)(Pz + (long)gc * Nn + k0);
            vb.x = f2tf32(vb.x); vb.y = f2tf32(vb.y);
            vb.z = f2tf32(vb.z); vb.w = f2tf32(vb.w);
            rb[l] = vb;
        }
    };

    load_chunk(0);

    for (int j = 0; j < NCHUNK; j++) {
        __syncthreads();
#pragma unroll
        for (int l = 0; l < 4; l++) {
            int linear = tid + l * 256;
            int row = linear >> 3, c4 = linear & 7;
            *(float4*)(As + row * LDK + c4 * 4) = ra[l];
            *(float4*)(Bs + row * LDK + c4 * 4) = rb[l];
        }
        __syncthreads();
        if (j + 1 < NCHUNK) load_chunk(j + 1);

#pragma unroll
        for (int ks = 0; ks < 4; ks++) {
            int kk = ks * 8;
            uint32_t afr[2][4];
#pragma unroll
            for (int fm = 0; fm < 2; fm++) {
                int rm = warp_m * 32 + fm * 16;
                const float* ab = As + (rm + g) * LDK + kk + tig;
                afr[fm][0] = __float_as_uint(ab[0]);
                afr[fm][1] = __float_as_uint(ab[8 * LDK]);
                afr[fm][2] = __float_as_uint(ab[4]);
                afr[fm][3] = __float_as_uint(ab[8 * LDK + 4]);
            }
#pragma unroll
            for (int fn = 0; fn < 8; fn++) {
                int nb = warp_n * 64 + fn * 8 + g;
                const float* bb = Bs + nb * LDK + kk + tig;
                uint32_t b0 = __float_as_uint(bb[0]);
                uint32_t b1 = __float_as_uint(bb[4]);
                mma_tf32(acc[0][fn], afr[0], b0, b1);
                mma_tf32(acc[1][fn], afr[1], b0, b1);
            }
        }
    }

    const float* Pprev_z = sub ? (Pprev + (long)z * NCOL * Nn) : nullptr;
    float* Pout_z = Pout ? (Pout + (long)z * NCOL * Nn) : nullptr;
#pragma unroll
    for (int fm = 0; fm < 2; fm++) {
#pragma unroll
        for (int fn = 0; fn < 8; fn++) {
            int m  = m0 + warp_m * 32 + fm * 16 + g;
            int gc = nt * 128 + warp_n * 64 + fn * 8 + tig * 2;
#pragma unroll
            for (int q = 0; q < 4; q++) {
                int mm = m + ((q >= 2) ? 8 : 0);
                int cc = gc + (q & 1);
                if (mm >= Nn) continue;
                float v = alpha * acc[fm][fn][q];
                if (sub) v -= Pprev_z[(long)cc * Nn + mm];
                int b = cc / XIN_, c = cc % XIN_;
                g_xg[(((long)z * Bq + b) * Nn + mm) * IG + out_off + c] = v;
                if (Pout_z) Pout_z[(long)cc * Nn + mm] = v;
            }
        }
    }
}

// ===========================================================================
// Kernel 3: fused gate hypernet. R13->R14: f32x2 packed FMA.
//   combine: d-pairs (c pairs loaded as b64 from smem, wgv pairs via mov.b64)
//   apply:   batch-pairs (x pairs loaded as b64 from smem, w broadcast pack)
// cp.async ring unchanged from R12. 128 thr, GGG=4, 3 blocks/SM.
// ===========================================================================
#define GGG 4
#define RING_OFF   (GGG * IG * 8 + GGG * Dd)       // floats: 7744
#define GATE_SMEM  ((RING_OFF + 4 * Dd * OG) * 4)  // + 4 stages * 2048 floats

__global__ __launch_bounds__(128, 3)
void gate_kernel(const float* __restrict__ e1, const float* __restrict__ e2,
                 const float* __restrict__ e3, const float* __restrict__ me,
                 const float* __restrict__ Wg, const float* __restrict__ Bg,
                 const float* __restrict__ st1, const float* __restrict__ st2,
                 const float* __restrict__ st3) {
    extern __shared__ float sm[];
    float* x_s  = sm;                      // [GGG][IG][8]
    float* c_s  = sm + GGG * IG * 8;       // [GGG][16]
    float* ring = sm + RING_OFF;           // [4][16][128]
    uint32_t ring_u32 = smem_u32(ring);

    int z = blockIdx.y;
    int n0 = blockIdx.x * GGG;
    const float* emb = (z == 0) ? e1 : (z == 1) ? e2 : e3;
    const float* st  = (z == 0) ? st1 : (z == 1) ? st2 : st3;

    int tid = threadIdx.x;

    auto issue_stage = [&](int i, int slot) {
#pragma unroll
        for (int l = 0; l < 4; l++) {
            int seg = tid + l * 128;        // 0..511 (16B segments)
            int d   = seg >> 5;             // 0..15
            int c4  = seg & 31;             // 16B chunk in 512B row
            cp_async16(ring_u32 + (uint32_t)(slot * 2048 + d * 128 + c4 * 4) * 4,
                       Wg + (long)d * IG * OG + (long)i * OG + c4 * 4);
        }
        CP_COMMIT();
    };

    issue_stage(0, 0);
    issue_stage(1, 1);
    issue_stage(2, 2);

    if (tid < GGG * Dd) {   // 64 <= 128
        int g = tid >> 4, d = tid & 15;
        c_s[tid] = emb[(n0 + g) * Dd + d] * me[z * Dd + d];
    }
    for (int idx = tid; idx < GGG * 8 * IG; idx += 128) {
        int i = idx % IG;
        int t = idx / IG;
        int g = t % GGG, b = t / GGG;
        x_s[(g * IG + i) * 8 + b] =
            g_xg[(((long)z * Bq + b) * Nn + n0 + g) * IG + i];
    }
    __syncthreads();

    int o = tid;  // 0..127

    // packed per-node coefficient d-pairs (c_s is 8B-aligned, pairs contiguous)
    u64t cpk[GGG][8];
#pragma unroll
    for (int g = 0; g < GGG; g++)
#pragma unroll
        for (int h = 0; h < 8; h++)
            cpk[g][h] = *(const u64t*)(c_s + g * 16 + h * 2);

    u64t accp[GGG][4];
#pragma unroll
    for (int g = 0; g < GGG; g++)
#pragma unroll
        for (int q = 0; q < 4; q++) accp[g][q] = 0ULL;

    for (int i = 0; i < IG; i++) {
        int slot = i & 3;
        CP_WAIT2();
        __syncthreads();

        float wv[16];
        const float* rs = ring + slot * 2048 + o;
#pragma unroll
        for (int d = 0; d < 16; d++) wv[d] = rs[d * 128];

        if (i + 3 < IG) issue_stage(i + 3, (i + 3) & 3);

        u64t wpk[8];
#pragma unroll
        for (int h = 0; h < 8; h++) wpk[h] = pack2(wv[2 * h], wv[2 * h + 1]);

#pragma unroll
        for (int g = 0; g < GGG; g++) {
            u64t s = 0ULL;
#pragma unroll
            for (int h = 0; h < 8; h++) ffma2(s, cpk[g][h], wpk[h]);
            float slo, shi; unpack2(slo, shi, s);
            u64t wb = pack2(slo + shi, slo + shi);
            const u64t* xp = (const u64t*)(x_s + (g * IG + i) * 8);
#pragma unroll
            for (int q = 0; q < 4; q++) ffma2(accp[g][q], wb, xp[q]);
        }
    }

#pragma unroll
    for (int g = 0; g < GGG; g++) {
        int n = n0 + g;
        float accf[8];
#pragma unroll
        for (int q = 0; q < 4; q++) unpack2(accf[2 * q], accf[2 * q + 1], accp[g][q]);
        float bias = 0.f;
#pragma unroll
        for (int d = 0; d < 16; d++) bias += c_s[g * 16 + d] * Bg[d * OG + o];
#pragma unroll
        for (int b = 0; b < 8; b++) {
            float v = accf[b] + bias;
            float sg = 1.f / (1.f + __expf(-v));
            if (o < Hh) {
                float stv = st[((long)b * Nn + n) * Hh + o];
                float zs = sg * stv;
                g_xg[(((long)z * Bq + b) * Nn + n) * IG + CIN_ + o] = zs;
                g_P0[((long)z * NCOL + b * XIN_ + CIN_ + o) * Nn + n] = zs;
            } else {
                g_r[(((long)z * Bq + b) * Nn + n) * Hh + (o - Hh)] = sg;
            }
        }
    }
}

// ===========================================================================
// Kernel 4: fused update hypernet + GRU mix. R13->R14: cp.async ring for Wu
// (same structure as gate) + f32x2 packing. GGU=4, 128 thr = (o:64)x(gh:2),
// gh owns 2 nodes. smem 47.4KB -> 3 blocks/SM.
// ===========================================================================
#define GGU 4
#define URING_OFF  (GGU * IG * 8 + GGU * Dd)        // floats: 7744
#define UPD_SMEM   ((URING_OFF + 4 * Dd * OU) * 4)  // + 4 stages * 1024 floats

__global__ __launch_bounds__(128, 3)
void update_kernel(const float* __restrict__ e1, const float* __restrict__ e2,
                   const float* __restrict__ e3, const float* __restrict__ me,
                   const float* __restrict__ Wu, const float* __restrict__ Bu,
                   const float* __restrict__ st1, const float* __restrict__ st2,
                   const float* __restrict__ st3, float* __restrict__ out) {
    extern __shared__ float sm[];
    float* x_s  = sm;                      // [GGU][IG][8]
    float* c_s  = sm + GGU * IG * 8;       // [GGU][16]
    float* ring = sm + URING_OFF;          // [4][16][64]
    uint32_t ring_u32 = smem_u32(ring);

    int z = blockIdx.y;
    int n0 = blockIdx.x * GGU;
    const float* emb = (z == 0) ? e1 : (z == 1) ? e2 : e3;
    const float* st  = (z == 0) ? st1 : (z == 1) ? st2 : st3;

    int tid = threadIdx.x;

    auto issue_stage = [&](int i, int slot) {
#pragma unroll
        for (int l = 0; l < 2; l++) {
            int seg = tid + l * 128;        // 0..255 (16B segments)
            int d   = seg >> 4;             // 0..15
            int c4  = seg & 15;             // 16B chunk in 256B row
            cp_async16(ring_u32 + (uint32_t)(slot * 1024 + d * 64 + c4 * 4) * 4,
                       Wu + (long)d * IG * OU + (long)i * OU + c4 * 4);
        }
        CP_COMMIT();
    };

    issue_stage(0, 0);
    issue_stage(1, 1);
    issue_stage(2, 2);

    if (tid < GGU * Dd) {   // 64 <= 128
        int g = tid >> 4, d = tid & 15;
        c_s[tid] = emb[(n0 + g) * Dd + d] * me[z * Dd + d];
    }
    for (int idx = tid; idx < GGU * 8 * IG; idx += 128) {
        int i = idx % IG;
        int t = idx / IG;
        int g = t % GGU, b = t / GGU;
        x_s[(g * IG + i) * 8 + b] =
            g_xg[(((long)z * Bq + b) * Nn + n0 + g) * IG + i];
    }
    __syncthreads();

    int o  = tid & 63;        // output column
    int gh = tid >> 6;        // node half: nodes {gh*2, gh*2+1}
    int gbase = gh * 2;

    u64t cpk[2][8];
#pragma unroll
    for (int g = 0; g < 2; g++)
#pragma unroll
        for (int h = 0; h < 8; h++)
            cpk[g][h] = *(const u64t*)(c_s + (gbase + g) * 16 + h * 2);

    u64t accp[2][4];
#pragma unroll
    for (int g = 0; g < 2; g++)
#pragma unroll
        for (int q = 0; q < 4; q++) accp[g][q] = 0ULL;

    for (int i = 0; i < IG; i++) {
        int slot = i & 3;
        CP_WAIT2();
        __syncthreads();

        float wv[16];
        const float* rs = ring + slot * 1024 + o;
#pragma unroll
        for (int d = 0; d < 16; d++) wv[d] = rs[d * 64];

        if (i + 3 < IG) issue_stage(i + 3, (i + 3) & 3);

        u64t wpk[8];
#pragma unroll
        for (int h = 0; h < 8; h++) wpk[h] = pack2(wv[2 * h], wv[2 * h + 1]);

#pragma unroll
        for (int g = 0; g < 2; g++) {
            u64t s = 0ULL;
#pragma unroll
            for (int h = 0; h < 8; h++) ffma2(s, cpk[g][h], wpk[h]);
            float slo, shi; unpack2(slo, shi, s);
            u64t wb = pack2(slo + shi, slo + shi);
            const u64t* xp = (const u64t*)(x_s + ((gbase + g) * IG + i) * 8);
#pragma unroll
            for (int q = 0; q < 4; q++) ffma2(accp[g][q], wb, xp[q]);
        }
    }

#pragma unroll
    for (int g = 0; g < 2; g++) {
        int n = n0 + gbase + g;
        float accf[8];
#pragma unroll
        for (int q = 0; q < 4; q++) unpack2(accf[2 * q], accf[2 * q + 1], accp[g][q]);
        float bias = 0.f;
#pragma unroll
        for (int d = 0; d < 16; d++) bias += c_s[(gbase + g) * 16 + d] * Bu[d * OU + o];
#pragma unroll
        for (int b = 0; b < 8; b++) {
            float hc = tanhf(accf[b] + bias);
            long hidx = (((long)z * Bq + b) * Nn + n) * Hh + o;
            float r = g_r[hidx];
            float stv = st[((long)b * Nn + n) * Hh + o];
            out[hidx] = r * stv + (1.f - r) * hc;
        }
    }
}

// ===========================================================================
extern "C" void kernel_launch(void* const* d_in, const int* in_sizes, int n_in,
                              void* d_out, int out_size) {
    const float* x1 = (const float*)d_in[0];
    const float* x2 = (const float*)d_in[1];
    const float* x3 = (const float*)d_in[2];
    const float* s1 = (const float*)d_in[3];
    const float* s2 = (const float*)d_in[4];
    const float* s3 = (const float*)d_in[5];
    const float* A1 = (const float*)d_in[6];
    const float* A2 = (const float*)d_in[7];
    const float* A3 = (const float*)d_in[8];
    const float* e1 = (const float*)d_in[9];
    const float* e2 = (const float*)d_in[10];
    const float* e3 = (const float*)d_in[11];
    const float* me = (const float*)d_in[12];
    const float* Wg = (const float*)d_in[13];
    const float* Bg = (const float*)d_in[14];
    const float* Wu = (const float*)d_in[15];
    const float* Bu = (const float*)d_in[16];
    float* out = (float*)d_out;

    cudaFuncSetAttribute((const void*)gate_kernel,
                         cudaFuncAttributeMaxDynamicSharedMemorySize, GATE_SMEM);
    cudaFuncSetAttribute((const void*)update_kernel,
                         cudaFuncAttributeMaxDynamicSharedMemorySize, UPD_SMEM);

    float* P0;  cudaGetSymbolAddress((void**)&P0, g_P0);
    float* P1;  cudaGetSymbolAddress((void**)&P1, g_P1);

    dim3 gemm_grid(8, 5, 3);              // M-tiles x N-tiles x modes
    dim3 gg(Nn / GGG, 3);                 // 250 x 3
    dim3 gu(Nn / GGU, 3);                 // 250 x 3

    // ---- gate GCN ----
    concat_kernel<<<512, 256>>>(x1, x2, x3, s1, s2, s3);
    // t1 = S @ xs            -> g_xg[80:160] + packed P1
    gemm_tf32_kernel<<<gemm_grid, 256>>>(A1, A2, A3, P0, nullptr, P1, 80, 1.f, 0);
    // t2 = 2 S @ t1 - xs     -> g_xg[160:240]
    gemm_tf32_kernel<<<gemm_grid, 256>>>(A1, A2, A3, P1, P0, nullptr, 160, 2.f, 1);
    gate_kernel<<<gg, 128, GATE_SMEM>>>(e1, e2, e3, me, Wg, Bg, s1, s2, s3);
    // ---- candidate GCN (P0 cols 16:80 now hold z*state; cols 0:16 still x) ----
    gemm_tf32_kernel<<<gemm_grid, 256>>>(A1, A2, A3, P0, nullptr, P1, 80, 1.f, 0);
    gemm_tf32_kernel<<<gemm_grid, 256>>>(A1, A2, A3, P1, P0, nullptr, 160, 2.f, 1);
    update_kernel<<<gu, 128, UPD_SMEM>>>(e1, e2, e3, me, Wu, Bu, s1, s2, s3, out);
}